// round 14
// baseline (speedup 1.0000x reference)
#include <cuda_runtime.h>

// ---------------------------------------------------------------------------
// SpatioTemporalGNNLayer: out = relu(conv3x3(x,Ww)+Wb + conv3x3(agg,Bw)+Bb)
// agg[dst] = mean over incoming edges of x[src].
//
// Fused per-node kernel, f32x2 in native 64-bit registers. ONE 256-thread
// CTA per SM (255-reg budget): thread = 8 cos x 16 px, acc = 64 ull regs,
// 8-way ci split + 3-step smem tree reduction. LSU width-model optimized:
// conv is fma-bound (82 LSU cyc vs 96 fma cyc per warp-(ci,r)).
// ---------------------------------------------------------------------------

#define NNODES 4096
#define NODE_ELEMS 4096          // 16*16*16
#define RS 36                    // row: [0,x0..x15,0,pad,pad | x0..x15] (144B)
#define CHS (18*RS)              // 648 floats per channel image
#define IMG_FLOATS (32*CHS)      // 20736 (x 16ch + agg 16ch)
#define WT_FLOAT2 2304           // 144q x 16co duplicated pairs (one conv)
#define NMASK (NNODES-1)

typedef unsigned long long ull;

__device__ int g_deg[NNODES];
__device__ int g_cur[NNODES];
__device__ int g_off[NNODES + 1];
__device__ int g_srcs[16384 * 4];
__device__ int g_is64;

// ---------------------------------------------------------------------------
__global__ void prep_kernel(const int* __restrict__ ei32, int E) {
    int i = blockIdx.x * blockDim.x + threadIdx.x;
    if (i < NNODES) { g_deg[i] = 0; g_cur[i] = 0; }
    if (blockIdx.x == 0 && threadIdx.x < 32) {
        int n = (E < 32) ? E : 32;
        int odd = (threadIdx.x < n) ? ei32[2 * threadIdx.x + 1] : 0;
        unsigned nz = __ballot_sync(0xffffffffu, odd != 0);
        if (threadIdx.x == 0) g_is64 = (nz == 0);
    }
}

__device__ __forceinline__ int load_idx(const int* ei32, int pos) {
    return g_is64 ? (ei32[2 * pos] & NMASK) : (ei32[pos] & NMASK);
}

__global__ void count_kernel(const int* __restrict__ ei32, int E) {
    int e = blockIdx.x * blockDim.x + threadIdx.x;
    if (e < E) atomicAdd(&g_deg[load_idx(ei32, E + e)], 1);
}

__global__ void scanfill_kernel(const int* __restrict__ ei32, int E) {
    __shared__ int wsum[32];
    int t = threadIdx.x;
    int lane = t & 31, wid = t >> 5;
    int4 v = ((const int4*)g_deg)[t];
    int sum = v.x + v.y + v.z + v.w;
    int s = sum;
#pragma unroll
    for (int d = 1; d < 32; d <<= 1) {
        int n = __shfl_up_sync(0xffffffffu, s, d);
        if (lane >= d) s += n;
    }
    if (lane == 31) wsum[wid] = s;
    __syncthreads();
    if (wid == 0) {
        int ws = wsum[lane];
#pragma unroll
        for (int d = 1; d < 32; d <<= 1) {
            int n = __shfl_up_sync(0xffffffffu, ws, d);
            if (lane >= d) ws += n;
        }
        wsum[lane] = ws;
    }
    __syncthreads();
    int excl = ((wid > 0) ? wsum[wid - 1] : 0) + s - sum;
    g_off[4 * t + 0] = excl;
    g_off[4 * t + 1] = excl + v.x;
    g_off[4 * t + 2] = excl + v.x + v.y;
    g_off[4 * t + 3] = excl + v.x + v.y + v.z;
    if (t == 1023) g_off[NNODES] = wsum[31];
    __syncthreads();
    for (int e = t; e < E; e += 1024) {
        int sc = load_idx(ei32, e);
        int d  = load_idx(ei32, E + e);
        int pos = g_off[d] + atomicAdd(&g_cur[d], 1);
        g_srcs[pos] = sc;
    }
}

// ---------------------------------------------------------------------------
__device__ __forceinline__ void ffma2u(ull& d, ull a, ull b) {
    asm("fma.rn.f32x2 %0, %1, %2, %0;" : "+l"(d) : "l"(a), "l"(b));
}
__device__ __forceinline__ void fadd2u(ull& d, ull a) {
    asm("add.rn.f32x2 %0, %0, %1;" : "+l"(d) : "l"(a));
}
__device__ __forceinline__ float2 u2f(ull v) {
    float2 f;
    asm("mov.b64 {%0, %1}, %2;" : "=f"(f.x), "=f"(f.y) : "l"(v));
    return f;
}
__device__ __forceinline__ ull f2u(float lo, float hi) {
    ull v;
    asm("mov.b64 %0, {%1, %2};" : "=l"(v) : "f"(lo), "f"(hi));
    return v;
}

// 2-ci-slice conv in ull domain: 8 cos x 16 px (8 pairs) of one output row.
// Row layout (36 floats): [0, x0..x15, 0, pad, pad | x0..x15]
//   P[k] = pair at words 2k (taps -1/+1), S[k] at words 20+2k (tap 0).
// Weights wt[q*16 + co] float2 = (w,w), q = ci*9 + r*3 + t.
__device__ __forceinline__ void conv_slice(const float* __restrict__ img,
                                           const float* __restrict__ wt,
                                           int ci0, int row, int co0,
                                           ull acc[8][8]) {
#pragma unroll 1
    for (int cl = 0; cl < 2; cl++) {
        int ci = ci0 + cl;
        const float* ch = img + ci * CHS;
#pragma unroll 1
        for (int r = 0; r < 3; r++) {
            const float* bp = ch + (row + r) * RS;
            ulonglong2 pA = *(const ulonglong2*)(bp);
            ulonglong2 pB = *(const ulonglong2*)(bp + 4);
            ulonglong2 pC = *(const ulonglong2*)(bp + 8);
            ulonglong2 pD = *(const ulonglong2*)(bp + 12);
            ull        p8 = *(const ull*)(bp + 16);
            ulonglong2 sA = *(const ulonglong2*)(bp + 20);
            ulonglong2 sB = *(const ulonglong2*)(bp + 24);
            ulonglong2 sC = *(const ulonglong2*)(bp + 28);
            ulonglong2 sD = *(const ulonglong2*)(bp + 32);
            ull P[9] = { pA.x, pA.y, pB.x, pB.y, pC.x, pC.y, pD.x, pD.y, p8 };
            ull S[8] = { sA.x, sA.y, sB.x, sB.y, sC.x, sC.y, sD.x, sD.y };
            const ull* wr = (const ull*)(wt + ((ci * 9 + r * 3) * 16 + co0) * 2);
#pragma unroll
            for (int t = 0; t < 3; t++) {
                ulonglong2 w01 = *(const ulonglong2*)(wr + t * 16);
                ulonglong2 w23 = *(const ulonglong2*)(wr + t * 16 + 2);
                ulonglong2 w45 = *(const ulonglong2*)(wr + t * 16 + 4);
                ulonglong2 w67 = *(const ulonglong2*)(wr + t * 16 + 6);
                ull w[8] = { w01.x, w01.y, w23.x, w23.y,
                             w45.x, w45.y, w67.x, w67.y };
#pragma unroll
                for (int c = 0; c < 8; c++) {
#pragma unroll
                    for (int j = 0; j < 8; j++) {
                        ull op = (t == 0) ? P[j] : (t == 1) ? S[j] : P[j + 1];
                        ffma2u(acc[c][j], w[c], op);
                    }
                }
            }
        }
    }
}

__global__ __launch_bounds__(256, 1) void gnn_main_kernel(
    const float* __restrict__ x,
    const float* __restrict__ Ww, const float* __restrict__ Wbias,
    const float* __restrict__ Bw, const float* __restrict__ Bbias,
    float* __restrict__ out) {
    extern __shared__ float sm[];
    float* sImg = sm;                   // 20736 floats
    float* sWt  = sm + IMG_FLOATS;      // 4608 floats (2304 float2, one conv)

    int tid  = threadIdx.x;
    int node = blockIdx.x;

    // targeted pad zeroing: rows 0 and 17 of every channel (9 float4 each)
    for (int i = tid; i < 32 * 18; i += 256) {
        int ch = i / 18, k = i % 18;
        int rbase = (k < 9) ? 0 : 17 * RS;
        int q = (k < 9) ? k : (k - 9);
        *(float4*)(sImg + ch * CHS + rbase + q * 4) = make_float4(0.f, 0.f, 0.f, 0.f);
    }
    // words 0 and 17 of rows 1..16 of every channel
    for (int i = tid; i < 32 * 16; i += 256) {
        int ch = i >> 4, y = i & 15;
        float* b = sImg + ch * CHS + (y + 1) * RS;
        b[0] = 0.f; b[17] = 0.f;
    }
    // stage phase-A (Ww): float2 slot q*16+co = (w,w)
    for (int i = tid; i < WT_FLOAT2; i += 256) {
        int co = i & 15, q = i >> 4;
        float v = Ww[co * 144 + q];
        sWt[2 * i] = v; sWt[2 * i + 1] = v;
    }

    // gather-mean over incoming edges: 4 float4 per thread (regs)
    const float4* xp = (const float4*)(x + (size_t)node * NODE_ELEMS);
    float4 a[4];
#pragma unroll
    for (int k = 0; k < 4; k++) a[k] = make_float4(0.f, 0.f, 0.f, 0.f);
    int beg = g_off[node], end = g_off[node + 1];
    for (int e = beg; e < end; e++) {
        int sc = g_srcs[e] & NMASK;
        const float4* sp = (const float4*)(x + (size_t)sc * NODE_ELEMS);
#pragma unroll
        for (int k = 0; k < 4; k++) {
            float4 v = __ldg(&sp[tid + 256 * k]);
            a[k].x += v.x; a[k].y += v.y; a[k].z += v.z; a[k].w += v.w;
        }
    }
    float inv = 1.0f / (float)max(end - beg, 1);

    __syncthreads();   // pads zeroed + Ww staged

    // scatter x + agg into dual-alignment rows
#pragma unroll
    for (int k = 0; k < 4; k++) {
        int i4  = tid + 256 * k;
        int ci  = i4 >> 6;
        int rem = i4 & 63;
        int y   = rem >> 2;
        int m   = (rem & 3) * 4;
        float* bx = sImg + ci * CHS + (y + 1) * RS;
        float* ba = sImg + (16 + ci) * CHS + (y + 1) * RS;
        float4 xv = xp[i4];
        bx[1 + m] = xv.x; bx[2 + m] = xv.y; bx[3 + m] = xv.z; bx[4 + m] = xv.w;
        *(float4*)(bx + 20 + m) = xv;
        float4 av = make_float4(a[k].x * inv, a[k].y * inv, a[k].z * inv, a[k].w * inv);
        ba[1 + m] = av.x; ba[2 + m] = av.y; ba[3 + m] = av.z; ba[4 + m] = av.w;
        *(float4*)(ba + 20 + m) = av;
    }
    __syncthreads();

    // thread map: tid = row | cog<<4 | cig<<5
    // warp = 16 rows x 2 cogs (octets = 8 distinct rows -> conflict-free LDS)
    int lane = tid & 31;
    int row  = tid & 15;
    int cog  = (tid >> 4) & 1;
    int cig  = tid >> 5;           // 0..7 = warp id
    int co0  = cog * 8;
    int ci0  = cig * 2;

    // bias folded into acc init on the cig==0 warp only
    ull acc[8][8];
#pragma unroll
    for (int c = 0; c < 8; c++) {
        float bz = (cig == 0) ? (__ldg(&Wbias[co0 + c]) + __ldg(&Bbias[co0 + c])) : 0.f;
        ull b2 = f2u(bz, bz);
#pragma unroll
        for (int j = 0; j < 8; j++) acc[c][j] = b2;
    }

    // phase A: conv(x, Ww) over this warp's 2-ci slice
    conv_slice(sImg, sWt, ci0, row, co0, acc);

    __syncthreads();   // done reading Ww
    for (int i = tid; i < WT_FLOAT2; i += 256) {
        int co = i & 15, q = i >> 4;
        float v = Bw[co * 144 + q];
        sWt[2 * i] = v; sWt[2 * i + 1] = v;
    }
    __syncthreads();

    // phase B: conv(agg, Bw)
    conv_slice(sImg + 16 * CHS, sWt, ci0, row, co0, acc);

    // 3-step tree reduction over 8 ci-groups (reuse sImg; max 64KB)
    // buf layout: [(c*4 + jj) * 128 + slot] ulonglong2, slot = k*32 + lane
    __syncthreads();
    ulonglong2* buf = (ulonglong2*)sImg;
#pragma unroll 1
    for (int s = 4; s >= 1; s >>= 1) {
        if (cig >= s && cig < 2 * s) {
            int slot = (cig - s) * 32 + lane;
#pragma unroll
            for (int c = 0; c < 8; c++)
#pragma unroll
                for (int jj = 0; jj < 4; jj++)
                    buf[(c * 4 + jj) * 128 + slot] =
                        make_ulonglong2(acc[c][2 * jj], acc[c][2 * jj + 1]);
        }
        __syncthreads();
        if (cig < s) {
            int slot = cig * 32 + lane;
#pragma unroll
            for (int c = 0; c < 8; c++)
#pragma unroll
                for (int jj = 0; jj < 4; jj++) {
                    ulonglong2 rp = buf[(c * 4 + jj) * 128 + slot];
                    fadd2u(acc[c][2 * jj],     rp.x);
                    fadd2u(acc[c][2 * jj + 1], rp.y);
                }
        }
        __syncthreads();
    }

    // relu + store: cig==0 warp writes 8 cos x 16 px each
    if (cig == 0) {
#pragma unroll
        for (int c = 0; c < 8; c++) {
            float* o = out + (size_t)node * NODE_ELEMS + (co0 + c) * 256 + row * 16;
#pragma unroll
            for (int q = 0; q < 4; q++) {
                float2 v0 = u2f(acc[c][2 * q]);
                float2 v1 = u2f(acc[c][2 * q + 1]);
                ((float4*)o)[q] = make_float4(fmaxf(v0.x, 0.f), fmaxf(v0.y, 0.f),
                                              fmaxf(v1.x, 0.f), fmaxf(v1.y, 0.f));
            }
        }
    }
}

// ---------------------------------------------------------------------------
extern "C" void kernel_launch(void* const* d_in, const int* in_sizes, int n_in,
                              void* d_out, int out_size) {
    const float* x   = (const float*)d_in[0];
    const int*   ei  = (const int*)d_in[1];   // int32 view; prep detects dtype
    const float* Ww  = (const float*)d_in[2];
    const float* Wb  = (const float*)d_in[3];
    const float* Bw  = (const float*)d_in[4];
    const float* Bb  = (const float*)d_in[5];
    float*       out = (float*)d_out;

    int E = in_sizes[1] / 2;
    int N = in_sizes[0] / NODE_ELEMS;

    prep_kernel<<<(NNODES + 255) / 256, 256>>>(ei, E);
    count_kernel<<<(E + 255) / 256, 256>>>(ei, E);
    scanfill_kernel<<<1, 1024>>>(ei, E);

    int smem_bytes = (IMG_FLOATS + 2 * WT_FLOAT2) * (int)sizeof(float);  // 101376
    cudaFuncSetAttribute(gnn_main_kernel,
                         cudaFuncAttributeMaxDynamicSharedMemorySize, smem_bytes);
    gnn_main_kernel<<<N, 256, smem_bytes>>>(x, Ww, Wb, Bw, Bb, out);
}

// round 15
// speedup vs baseline: 1.1407x; 1.1407x over previous
#include <cuda_runtime.h>

// ---------------------------------------------------------------------------
// SpatioTemporalGNNLayer: out = relu(conv3x3(x,Ww)+Wb + conv3x3(agg,Bw)+Bb)
// agg[dst] = mean over incoming edges of x[src].
//
// Fused per-node kernel, f32x2 in native 64-bit registers. ONE 256-thread
// CTA per SM (255-reg budget): thread = 8 cos x 16 px (acc = 64 ull regs),
// 8-way ci split + tree reduction. R15: conv blocks FULLY UNROLLED with
// compile-time offsets off hoisted base pointers -> no per-block IMAD chains,
// loads pipelined across blocks by ptxas.
// ---------------------------------------------------------------------------

#define NNODES 4096
#define NODE_ELEMS 4096          // 16*16*16
#define RS 36                    // row: [0,x0..x15,0,pad,pad | x0..x15] (144B)
#define CHS (18*RS)              // 648 floats per channel image
#define IMG_FLOATS (32*CHS)      // 20736 (x 16ch + agg 16ch)
#define WT_FLOAT2 2304           // 144q x 16co duplicated pairs (one conv)
#define NMASK (NNODES-1)

typedef unsigned long long ull;

__device__ int g_deg[NNODES];
__device__ int g_cur[NNODES];
__device__ int g_off[NNODES + 1];
__device__ int g_srcs[16384 * 4];
__device__ int g_is64;

// ---------------------------------------------------------------------------
__global__ void prep_kernel(const int* __restrict__ ei32, int E) {
    int i = blockIdx.x * blockDim.x + threadIdx.x;
    if (i < NNODES) { g_deg[i] = 0; g_cur[i] = 0; }
    if (blockIdx.x == 0 && threadIdx.x < 32) {
        int n = (E < 32) ? E : 32;
        int odd = (threadIdx.x < n) ? ei32[2 * threadIdx.x + 1] : 0;
        unsigned nz = __ballot_sync(0xffffffffu, odd != 0);
        if (threadIdx.x == 0) g_is64 = (nz == 0);
    }
}

__device__ __forceinline__ int load_idx(const int* ei32, int pos) {
    return g_is64 ? (ei32[2 * pos] & NMASK) : (ei32[pos] & NMASK);
}

__global__ void count_kernel(const int* __restrict__ ei32, int E) {
    int e = blockIdx.x * blockDim.x + threadIdx.x;
    if (e < E) atomicAdd(&g_deg[load_idx(ei32, E + e)], 1);
}

__global__ void scanfill_kernel(const int* __restrict__ ei32, int E) {
    __shared__ int wsum[32];
    int t = threadIdx.x;
    int lane = t & 31, wid = t >> 5;
    int4 v = ((const int4*)g_deg)[t];
    int sum = v.x + v.y + v.z + v.w;
    int s = sum;
#pragma unroll
    for (int d = 1; d < 32; d <<= 1) {
        int n = __shfl_up_sync(0xffffffffu, s, d);
        if (lane >= d) s += n;
    }
    if (lane == 31) wsum[wid] = s;
    __syncthreads();
    if (wid == 0) {
        int ws = wsum[lane];
#pragma unroll
        for (int d = 1; d < 32; d <<= 1) {
            int n = __shfl_up_sync(0xffffffffu, ws, d);
            if (lane >= d) ws += n;
        }
        wsum[lane] = ws;
    }
    __syncthreads();
    int excl = ((wid > 0) ? wsum[wid - 1] : 0) + s - sum;
    g_off[4 * t + 0] = excl;
    g_off[4 * t + 1] = excl + v.x;
    g_off[4 * t + 2] = excl + v.x + v.y;
    g_off[4 * t + 3] = excl + v.x + v.y + v.z;
    if (t == 1023) g_off[NNODES] = wsum[31];
    __syncthreads();
    for (int e = t; e < E; e += 1024) {
        int sc = load_idx(ei32, e);
        int d  = load_idx(ei32, E + e);
        int pos = g_off[d] + atomicAdd(&g_cur[d], 1);
        g_srcs[pos] = sc;
    }
}

// ---------------------------------------------------------------------------
__device__ __forceinline__ void ffma2u(ull& d, ull a, ull b) {
    asm("fma.rn.f32x2 %0, %1, %2, %0;" : "+l"(d) : "l"(a), "l"(b));
}
__device__ __forceinline__ void fadd2u(ull& d, ull a) {
    asm("add.rn.f32x2 %0, %0, %1;" : "+l"(d) : "l"(a));
}
__device__ __forceinline__ float2 u2f(ull v) {
    float2 f;
    asm("mov.b64 {%0, %1}, %2;" : "=f"(f.x), "=f"(f.y) : "l"(v));
    return f;
}
__device__ __forceinline__ ull f2u(float lo, float hi) {
    ull v;
    asm("mov.b64 %0, {%1, %2};" : "=l"(v) : "f"(lo), "f"(hi));
    return v;
}

// 2-ci-slice conv, FULLY UNROLLED: 8 cos x 16 px (8 pairs) of one output row.
// All smem offsets are compile-time immediates off bp0 / wp0.
// Row layout (36 floats): [0, x0..x15, 0, pad, pad | x0..x15]
//   P[k] = pair at words 2k (taps -1/+1), S[k] at words 20+2k (tap 0).
// Weights wt[q*16 + co] float2 = (w,w), q = ci*9 + r*3 + t.
__device__ __forceinline__ void conv_slice(const float* __restrict__ img,
                                           const float* __restrict__ wt,
                                           int ci0, int row, int co0,
                                           ull acc[8][8]) {
    const float* bp0 = img + ci0 * CHS + row * RS;
    const ull*   wp0 = (const ull*)(wt + (ci0 * 9 * 16 + co0) * 2);
#pragma unroll
    for (int cl = 0; cl < 2; cl++) {
#pragma unroll
        for (int r = 0; r < 3; r++) {
            const float* bp = bp0 + cl * CHS + r * RS;          // imm offsets
            const ull*   wr = wp0 + (cl * 9 + r * 3) * 16;      // imm offsets
            ulonglong2 pA = *(const ulonglong2*)(bp);
            ulonglong2 pB = *(const ulonglong2*)(bp + 4);
            ulonglong2 pC = *(const ulonglong2*)(bp + 8);
            ulonglong2 pD = *(const ulonglong2*)(bp + 12);
            ull        p8 = *(const ull*)(bp + 16);
            ulonglong2 sA = *(const ulonglong2*)(bp + 20);
            ulonglong2 sB = *(const ulonglong2*)(bp + 24);
            ulonglong2 sC = *(const ulonglong2*)(bp + 28);
            ulonglong2 sD = *(const ulonglong2*)(bp + 32);
            ull P[9] = { pA.x, pA.y, pB.x, pB.y, pC.x, pC.y, pD.x, pD.y, p8 };
            ull S[8] = { sA.x, sA.y, sB.x, sB.y, sC.x, sC.y, sD.x, sD.y };
#pragma unroll
            for (int t = 0; t < 3; t++) {
                ulonglong2 w01 = *(const ulonglong2*)(wr + t * 16);
                ulonglong2 w23 = *(const ulonglong2*)(wr + t * 16 + 2);
                ulonglong2 w45 = *(const ulonglong2*)(wr + t * 16 + 4);
                ulonglong2 w67 = *(const ulonglong2*)(wr + t * 16 + 6);
                ull w[8] = { w01.x, w01.y, w23.x, w23.y,
                             w45.x, w45.y, w67.x, w67.y };
#pragma unroll
                for (int c = 0; c < 8; c++) {
#pragma unroll
                    for (int j = 0; j < 8; j++) {
                        ull op = (t == 0) ? P[j] : (t == 1) ? S[j] : P[j + 1];
                        ffma2u(acc[c][j], w[c], op);
                    }
                }
            }
        }
    }
}

__global__ __launch_bounds__(256, 1) void gnn_main_kernel(
    const float* __restrict__ x,
    const float* __restrict__ Ww, const float* __restrict__ Wbias,
    const float* __restrict__ Bw, const float* __restrict__ Bbias,
    float* __restrict__ out) {
    extern __shared__ float sm[];
    float* sImg = sm;                   // 20736 floats
    float* sWt  = sm + IMG_FLOATS;      // 4608 floats (2304 float2, one conv)

    int tid  = threadIdx.x;
    int node = blockIdx.x;

    // targeted pad zeroing: rows 0 and 17 of every channel (9 float4 each)
    for (int i = tid; i < 32 * 18; i += 256) {
        int ch = i / 18, k = i % 18;
        int rbase = (k < 9) ? 0 : 17 * RS;
        int q = (k < 9) ? k : (k - 9);
        *(float4*)(sImg + ch * CHS + rbase + q * 4) = make_float4(0.f, 0.f, 0.f, 0.f);
    }
    // words 0 and 17 of rows 1..16 of every channel
    for (int i = tid; i < 32 * 16; i += 256) {
        int ch = i >> 4, y = i & 15;
        float* b = sImg + ch * CHS + (y + 1) * RS;
        b[0] = 0.f; b[17] = 0.f;
    }
    // stage phase-A (Ww): float2 slot q*16+co = (w,w)
    for (int i = tid; i < WT_FLOAT2; i += 256) {
        int co = i & 15, q = i >> 4;
        float v = Ww[co * 144 + q];
        sWt[2 * i] = v; sWt[2 * i + 1] = v;
    }

    // gather-mean over incoming edges: 4 float4 per thread (regs)
    const float4* xp = (const float4*)(x + (size_t)node * NODE_ELEMS);
    float4 a[4];
#pragma unroll
    for (int k = 0; k < 4; k++) a[k] = make_float4(0.f, 0.f, 0.f, 0.f);
    int beg = g_off[node], end = g_off[node + 1];
    for (int e = beg; e < end; e++) {
        int sc = g_srcs[e] & NMASK;
        const float4* sp = (const float4*)(x + (size_t)sc * NODE_ELEMS);
#pragma unroll
        for (int k = 0; k < 4; k++) {
            float4 v = __ldg(&sp[tid + 256 * k]);
            a[k].x += v.x; a[k].y += v.y; a[k].z += v.z; a[k].w += v.w;
        }
    }
    float inv = 1.0f / (float)max(end - beg, 1);

    __syncthreads();   // pads zeroed + Ww staged

    // scatter x + agg into dual-alignment rows
#pragma unroll
    for (int k = 0; k < 4; k++) {
        int i4  = tid + 256 * k;
        int ci  = i4 >> 6;
        int rem = i4 & 63;
        int y   = rem >> 2;
        int m   = (rem & 3) * 4;
        float* bx = sImg + ci * CHS + (y + 1) * RS;
        float* ba = sImg + (16 + ci) * CHS + (y + 1) * RS;
        float4 xv = xp[i4];
        bx[1 + m] = xv.x; bx[2 + m] = xv.y; bx[3 + m] = xv.z; bx[4 + m] = xv.w;
        *(float4*)(bx + 20 + m) = xv;
        float4 av = make_float4(a[k].x * inv, a[k].y * inv, a[k].z * inv, a[k].w * inv);
        ba[1 + m] = av.x; ba[2 + m] = av.y; ba[3 + m] = av.z; ba[4 + m] = av.w;
        *(float4*)(ba + 20 + m) = av;
    }
    __syncthreads();

    // thread map: tid = row | cog<<4 | cig<<5
    int lane = tid & 31;
    int row  = tid & 15;
    int cog  = (tid >> 4) & 1;
    int cig  = tid >> 5;           // 0..7 = warp id
    int co0  = cog * 8;
    int ci0  = cig * 2;

    // bias folded into acc init on the cig==0 warp only
    ull acc[8][8];
#pragma unroll
    for (int c = 0; c < 8; c++) {
        float bz = (cig == 0) ? (__ldg(&Wbias[co0 + c]) + __ldg(&Bbias[co0 + c])) : 0.f;
        ull b2 = f2u(bz, bz);
#pragma unroll
        for (int j = 0; j < 8; j++) acc[c][j] = b2;
    }

    // phase A: conv(x, Ww) over this warp's 2-ci slice
    conv_slice(sImg, sWt, ci0, row, co0, acc);

    __syncthreads();   // done reading Ww
    for (int i = tid; i < WT_FLOAT2; i += 256) {
        int co = i & 15, q = i >> 4;
        float v = Bw[co * 144 + q];
        sWt[2 * i] = v; sWt[2 * i + 1] = v;
    }
    __syncthreads();

    // phase B: conv(agg, Bw)
    conv_slice(sImg + 16 * CHS, sWt, ci0, row, co0, acc);

    // 3-step tree reduction over 8 ci-groups (reuse sImg; max 64KB)
    __syncthreads();
    ulonglong2* buf = (ulonglong2*)sImg;
#pragma unroll 1
    for (int s = 4; s >= 1; s >>= 1) {
        if (cig >= s && cig < 2 * s) {
            int slot = (cig - s) * 32 + lane;
#pragma unroll
            for (int c = 0; c < 8; c++)
#pragma unroll
                for (int jj = 0; jj < 4; jj++)
                    buf[(c * 4 + jj) * 128 + slot] =
                        make_ulonglong2(acc[c][2 * jj], acc[c][2 * jj + 1]);
        }
        __syncthreads();
        if (cig < s) {
            int slot = cig * 32 + lane;
#pragma unroll
            for (int c = 0; c < 8; c++)
#pragma unroll
                for (int jj = 0; jj < 4; jj++) {
                    ulonglong2 rp = buf[(c * 4 + jj) * 128 + slot];
                    fadd2u(acc[c][2 * jj],     rp.x);
                    fadd2u(acc[c][2 * jj + 1], rp.y);
                }
        }
        __syncthreads();
    }

    // relu + store: cig==0 warp writes 8 cos x 16 px each
    if (cig == 0) {
#pragma unroll
        for (int c = 0; c < 8; c++) {
            float* o = out + (size_t)node * NODE_ELEMS + (co0 + c) * 256 + row * 16;
#pragma unroll
            for (int q = 0; q < 4; q++) {
                float2 v0 = u2f(acc[c][2 * q]);
                float2 v1 = u2f(acc[c][2 * q + 1]);
                ((float4*)o)[q] = make_float4(fmaxf(v0.x, 0.f), fmaxf(v0.y, 0.f),
                                              fmaxf(v1.x, 0.f), fmaxf(v1.y, 0.f));
            }
        }
    }
}

// ---------------------------------------------------------------------------
extern "C" void kernel_launch(void* const* d_in, const int* in_sizes, int n_in,
                              void* d_out, int out_size) {
    const float* x   = (const float*)d_in[0];
    const int*   ei  = (const int*)d_in[1];   // int32 view; prep detects dtype
    const float* Ww  = (const float*)d_in[2];
    const float* Wb  = (const float*)d_in[3];
    const float* Bw  = (const float*)d_in[4];
    const float* Bb  = (const float*)d_in[5];
    float*       out = (float*)d_out;

    int E = in_sizes[1] / 2;
    int N = in_sizes[0] / NODE_ELEMS;

    prep_kernel<<<(NNODES + 255) / 256, 256>>>(ei, E);
    count_kernel<<<(E + 255) / 256, 256>>>(ei, E);
    scanfill_kernel<<<1, 1024>>>(ei, E);

    int smem_bytes = (IMG_FLOATS + 2 * WT_FLOAT2) * (int)sizeof(float);  // 101376
    cudaFuncSetAttribute(gnn_main_kernel,
                         cudaFuncAttributeMaxDynamicSharedMemorySize, smem_bytes);
    gnn_main_kernel<<<N, 256, smem_bytes>>>(x, Ww, Wb, Bw, Bb, out);
}

// round 16
// speedup vs baseline: 1.3877x; 1.2166x over previous
#include <cuda_runtime.h>

// ---------------------------------------------------------------------------
// SpatioTemporalGNNLayer via conv linearity:
//   U = conv(x, Ww) + Wb + Bb      (per node, fused kernel 1 -> d_out)
//   V = conv(x, Bw)                (per node, fused kernel 1 -> g_V)
//   out = relu(U[dst] + mean_{src in N(dst)} V[src])   (kernel 2, CSR gather)
// This removes the agg image + gather from the conv kernel entirely.
// Conv kernel: fma.rn.f32x2 (ull domain), 256 thr x 2 CTA/SM (16 warps),
// thread = 4 cos x 2 convs x 8 px, 2-way ci split + smem reduction.
// ---------------------------------------------------------------------------

#define NNODES 4096
#define NODE_ELEMS 4096          // 16*16*16
#define RS 36                    // row: [0,x0..x15,0,pad,pad | x0..x15] (144B)
#define CHS (18*RS)              // 648 floats per channel image
#define IMG_FLOATS (16*CHS)      // 10368 (single x image)
#define WT_FLOAT2 2304           // 144q x 16co duplicated pairs (one weight set)
#define NMASK (NNODES-1)

typedef unsigned long long ull;

__device__ int g_deg[NNODES];
__device__ int g_cur[NNODES];
__device__ int g_off[NNODES + 1];
__device__ int g_srcs[16384 * 4];
__device__ int g_is64;
__device__ float g_V[(size_t)NNODES * NODE_ELEMS];   // 67MB scratch for V

// ---------------------------------------------------------------------------
__global__ void prep_kernel(const int* __restrict__ ei32, int E) {
    int i = blockIdx.x * blockDim.x + threadIdx.x;
    if (i < NNODES) { g_deg[i] = 0; g_cur[i] = 0; }
    if (blockIdx.x == 0 && threadIdx.x < 32) {
        int n = (E < 32) ? E : 32;
        int odd = (threadIdx.x < n) ? ei32[2 * threadIdx.x + 1] : 0;
        unsigned nz = __ballot_sync(0xffffffffu, odd != 0);
        if (threadIdx.x == 0) g_is64 = (nz == 0);
    }
}

__device__ __forceinline__ int load_idx(const int* ei32, int pos) {
    return g_is64 ? (ei32[2 * pos] & NMASK) : (ei32[pos] & NMASK);
}

__global__ void count_kernel(const int* __restrict__ ei32, int E) {
    int e = blockIdx.x * blockDim.x + threadIdx.x;
    if (e < E) atomicAdd(&g_deg[load_idx(ei32, E + e)], 1);
}

__global__ void scanfill_kernel(const int* __restrict__ ei32, int E) {
    __shared__ int wsum[32];
    int t = threadIdx.x;
    int lane = t & 31, wid = t >> 5;
    int4 v = ((const int4*)g_deg)[t];
    int sum = v.x + v.y + v.z + v.w;
    int s = sum;
#pragma unroll
    for (int d = 1; d < 32; d <<= 1) {
        int n = __shfl_up_sync(0xffffffffu, s, d);
        if (lane >= d) s += n;
    }
    if (lane == 31) wsum[wid] = s;
    __syncthreads();
    if (wid == 0) {
        int ws = wsum[lane];
#pragma unroll
        for (int d = 1; d < 32; d <<= 1) {
            int n = __shfl_up_sync(0xffffffffu, ws, d);
            if (lane >= d) ws += n;
        }
        wsum[lane] = ws;
    }
    __syncthreads();
    int excl = ((wid > 0) ? wsum[wid - 1] : 0) + s - sum;
    g_off[4 * t + 0] = excl;
    g_off[4 * t + 1] = excl + v.x;
    g_off[4 * t + 2] = excl + v.x + v.y;
    g_off[4 * t + 3] = excl + v.x + v.y + v.z;
    if (t == 1023) g_off[NNODES] = wsum[31];
    __syncthreads();
    for (int e = t; e < E; e += 1024) {
        int sc = load_idx(ei32, e);
        int d  = load_idx(ei32, E + e);
        int pos = g_off[d] + atomicAdd(&g_cur[d], 1);
        g_srcs[pos] = sc;
    }
}

// ---------------------------------------------------------------------------
__device__ __forceinline__ void ffma2u(ull& d, ull a, ull b) {
    asm("fma.rn.f32x2 %0, %1, %2, %0;" : "+l"(d) : "l"(a), "l"(b));
}
__device__ __forceinline__ void fadd2u(ull& d, ull a) {
    asm("add.rn.f32x2 %0, %0, %1;" : "+l"(d) : "l"(a));
}
__device__ __forceinline__ float2 u2f(ull v) {
    float2 f;
    asm("mov.b64 {%0, %1}, %2;" : "=f"(f.x), "=f"(f.y) : "l"(v));
    return f;
}

// Apply one weight quadruple (4 cos) of one tap to 4 pixel pairs.
__device__ __forceinline__ void apply4(ull acc[4][4], const ull* wr, int off,
                                       const ull* op) {
    ulonglong2 wA = *(const ulonglong2*)(wr + off);
    ulonglong2 wB = *(const ulonglong2*)(wr + off + 2);
#pragma unroll
    for (int j = 0; j < 4; j++) {
        ffma2u(acc[0][j], wA.x, op[j]);
        ffma2u(acc[1][j], wA.y, op[j]);
        ffma2u(acc[2][j], wB.x, op[j]);
        ffma2u(acc[3][j], wB.y, op[j]);
    }
}

// 8-ci-slice dual conv: 4 cos x 2 weight sets x 8 px of one output row.
// Row layout (36 floats): [0, x0..x15, 0, pad, pad | x0..x15]
//   P[k] pairs at words 2k (taps -1/+1), S[k] at words 20+2k (tap 0); +8*half.
// Weights wt*[q*16 + co] = (w,w), q = ci*9 + r*3 + t (warp-uniform address).
__device__ __forceinline__ void conv_dual(const float* __restrict__ img,
                                          const float* __restrict__ wtW,
                                          const float* __restrict__ wtB,
                                          int ci0, int row, int half, int co0,
                                          ull accU[4][4], ull accV[4][4]) {
#pragma unroll 1
    for (int cl = 0; cl < 8; cl++) {
        int ci = ci0 + cl;
        const float* bp = img + ci * CHS + row * RS + 8 * half;
#pragma unroll
        for (int r = 0; r < 3; r++) {
            const float* rp = bp + r * RS;
            ulonglong2 pA = *(const ulonglong2*)(rp);
            ulonglong2 pB = *(const ulonglong2*)(rp + 4);
            ull        p4 = *(const ull*)(rp + 8);
            ulonglong2 sA = *(const ulonglong2*)(rp + 20);
            ulonglong2 sB = *(const ulonglong2*)(rp + 24);
            ull P[5] = { pA.x, pA.y, pB.x, pB.y, p4 };
            ull S[4] = { sA.x, sA.y, sB.x, sB.y };
            ull T0[4] = { P[0], P[1], P[2], P[3] };   // tap -1 operands
            ull T2[4] = { P[1], P[2], P[3], P[4] };   // tap +1 operands
            int qbase = (ci * 9 + r * 3) * 16 + co0;
            const ull* wrW = (const ull*)wtW + qbase;
            const ull* wrB = (const ull*)wtB + qbase;
            apply4(accU, wrW, 0,  T0);
            apply4(accU, wrW, 16, S);
            apply4(accU, wrW, 32, T2);
            apply4(accV, wrB, 0,  T0);
            apply4(accV, wrB, 16, S);
            apply4(accV, wrB, 32, T2);
        }
    }
}

__global__ __launch_bounds__(256, 2) void gnn_conv_kernel(
    const float* __restrict__ x,
    const float* __restrict__ Ww, const float* __restrict__ Wbias,
    const float* __restrict__ Bw, const float* __restrict__ Bbias,
    float* __restrict__ outU) {
    extern __shared__ float sm[];
    float* sImg = sm;                    // 10368 floats
    float* sWtW = sm + IMG_FLOATS;       // 4608 floats (2304 float2)
    float* sWtB = sWtW + 2 * WT_FLOAT2;  // 4608 floats

    int tid  = threadIdx.x;
    int node = blockIdx.x;

    // targeted pad zeroing: rows 0 and 17 of every channel (9 float4 each)
    for (int i = tid; i < 16 * 18; i += 256) {
        int ch = i / 18, k = i % 18;
        int rbase = (k < 9) ? 0 : 17 * RS;
        int q = (k < 9) ? k : (k - 9);
        *(float4*)(sImg + ch * CHS + rbase + q * 4) = make_float4(0.f, 0.f, 0.f, 0.f);
    }
    // words 0 and 17 of rows 1..16 of every channel
    if (tid < 16 * 16) {
        int ch = tid >> 4, y = tid & 15;
        float* b = sImg + ch * CHS + (y + 1) * RS;
        b[0] = 0.f; b[17] = 0.f;
    }
    // stage BOTH weight sets: float2 slot q*16+co = (w,w)
    for (int i = tid; i < WT_FLOAT2; i += 256) {
        int co = i & 15, q = i >> 4;
        float vw = Ww[co * 144 + q];
        float vb = Bw[co * 144 + q];
        sWtW[2 * i] = vw; sWtW[2 * i + 1] = vw;
        sWtB[2 * i] = vb; sWtB[2 * i + 1] = vb;
    }

    // load x[node] and scatter into dual-alignment rows (4 float4 / thread)
    const float4* xp = (const float4*)(x + (size_t)node * NODE_ELEMS);
    __syncthreads();   // pads zeroed before data stores
#pragma unroll
    for (int k = 0; k < 4; k++) {
        int i4  = tid + 256 * k;
        int ci  = i4 >> 6;
        int rem = i4 & 63;
        int y   = rem >> 2;
        int m   = (rem & 3) * 4;
        float* bx = sImg + ci * CHS + (y + 1) * RS;
        float4 xv = xp[i4];
        bx[1 + m] = xv.x; bx[2 + m] = xv.y; bx[3 + m] = xv.z; bx[4 + m] = xv.w;
        *(float4*)(bx + 20 + m) = xv;
    }
    __syncthreads();

    // thread map: lane -> row = lane&15, half = lane>>4
    //             warp w -> cog = w&3 (co0 = 4*cog), cih = w>>2 (ci0 = 8*cih)
    int lane = tid & 31;
    int w    = tid >> 5;
    int row  = lane & 15;
    int half = lane >> 4;
    int cog  = w & 3;
    int cih  = w >> 2;
    int co0  = cog * 4;
    int ci0  = cih * 8;

    ull accU[4][4], accV[4][4];
#pragma unroll
    for (int c = 0; c < 4; c++)
#pragma unroll
        for (int j = 0; j < 4; j++) { accU[c][j] = 0ull; accV[c][j] = 0ull; }

    conv_dual(sImg, sWtW, sWtB, ci0, row, half, co0, accU, accV);

    // 2-way cross-warp reduction (reuse sImg: 32KB needed, have 41KB)
    __syncthreads();
    ulonglong2* red = (ulonglong2*)sImg;   // [(uv*4+c)*2+jj][slot 128]
    int slot = cog * 32 + lane;            // 0..127
    if (cih == 1) {
#pragma unroll
        for (int c = 0; c < 4; c++) {
            red[((0 * 4 + c) * 2 + 0) * 128 + slot] = make_ulonglong2(accU[c][0], accU[c][1]);
            red[((0 * 4 + c) * 2 + 1) * 128 + slot] = make_ulonglong2(accU[c][2], accU[c][3]);
            red[((4 + c) * 2 + 0) * 128 + slot]     = make_ulonglong2(accV[c][0], accV[c][1]);
            red[((4 + c) * 2 + 1) * 128 + slot]     = make_ulonglong2(accV[c][2], accV[c][3]);
        }
    }
    __syncthreads();
    if (cih == 0) {
        float* gV = g_V + (size_t)node * NODE_ELEMS;
#pragma unroll
        for (int c = 0; c < 4; c++) {
            int co = co0 + c;
            float bz = __ldg(&Wbias[co]) + __ldg(&Bbias[co]);
            ulonglong2 r0 = red[((0 * 4 + c) * 2 + 0) * 128 + slot];
            ulonglong2 r1 = red[((0 * 4 + c) * 2 + 1) * 128 + slot];
            ulonglong2 r2 = red[((4 + c) * 2 + 0) * 128 + slot];
            ulonglong2 r3 = red[((4 + c) * 2 + 1) * 128 + slot];
            fadd2u(accU[c][0], r0.x); fadd2u(accU[c][1], r0.y);
            fadd2u(accU[c][2], r1.x); fadd2u(accU[c][3], r1.y);
            fadd2u(accV[c][0], r2.x); fadd2u(accV[c][1], r2.y);
            fadd2u(accV[c][2], r3.x); fadd2u(accV[c][3], r3.y);
            int off = co * 256 + row * 16 + 8 * half;
            float* oU = outU + (size_t)node * NODE_ELEMS + off;
            float2 u0 = u2f(accU[c][0]), u1 = u2f(accU[c][1]);
            float2 u2 = u2f(accU[c][2]), u3 = u2f(accU[c][3]);
            ((float4*)oU)[0] = make_float4(u0.x + bz, u0.y + bz, u1.x + bz, u1.y + bz);
            ((float4*)oU)[1] = make_float4(u2.x + bz, u2.y + bz, u3.x + bz, u3.y + bz);
            float2 v0 = u2f(accV[c][0]), v1 = u2f(accV[c][1]);
            float2 v2 = u2f(accV[c][2]), v3 = u2f(accV[c][3]);
            ((float4*)(gV + off))[0] = make_float4(v0.x, v0.y, v1.x, v1.y);
            ((float4*)(gV + off))[1] = make_float4(v2.x, v2.y, v3.x, v3.y);
        }
    }
}

// ---------------------------------------------------------------------------
// kernel 2: out = relu(U[dst] + mean_src V[src]); in-place on d_out (U).
__global__ __launch_bounds__(256) void gather_relu_kernel(float* __restrict__ out) {
    int tid  = threadIdx.x;
    int node = blockIdx.x;
    float* op = out + (size_t)node * NODE_ELEMS;

    float4 vs[4];
#pragma unroll
    for (int k = 0; k < 4; k++) vs[k] = make_float4(0.f, 0.f, 0.f, 0.f);

    int beg = g_off[node], end = g_off[node + 1];
    for (int e = beg; e < end; e++) {
        int sc = g_srcs[e] & NMASK;
        const float4* vp = (const float4*)(g_V + (size_t)sc * NODE_ELEMS);
#pragma unroll
        for (int k = 0; k < 4; k++) {
            float4 v = __ldg(&vp[tid + 256 * k]);
            vs[k].x += v.x; vs[k].y += v.y; vs[k].z += v.z; vs[k].w += v.w;
        }
    }
    float inv = 1.0f / (float)max(end - beg, 1);
#pragma unroll
    for (int k = 0; k < 4; k++) {
        float4 u = ((const float4*)op)[tid + 256 * k];
        ((float4*)op)[tid + 256 * k] = make_float4(
            fmaxf(u.x + vs[k].x * inv, 0.f), fmaxf(u.y + vs[k].y * inv, 0.f),
            fmaxf(u.z + vs[k].z * inv, 0.f), fmaxf(u.w + vs[k].w * inv, 0.f));
    }
}

// ---------------------------------------------------------------------------
extern "C" void kernel_launch(void* const* d_in, const int* in_sizes, int n_in,
                              void* d_out, int out_size) {
    const float* x   = (const float*)d_in[0];
    const int*   ei  = (const int*)d_in[1];   // int32 view; prep detects dtype
    const float* Ww  = (const float*)d_in[2];
    const float* Wb  = (const float*)d_in[3];
    const float* Bw  = (const float*)d_in[4];
    const float* Bb  = (const float*)d_in[5];
    float*       out = (float*)d_out;

    int E = in_sizes[1] / 2;
    int N = in_sizes[0] / NODE_ELEMS;

    prep_kernel<<<(NNODES + 255) / 256, 256>>>(ei, E);
    count_kernel<<<(E + 255) / 256, 256>>>(ei, E);
    scanfill_kernel<<<1, 1024>>>(ei, E);

    int smem_bytes = (IMG_FLOATS + 4 * WT_FLOAT2) * (int)sizeof(float);  // 78336
    cudaFuncSetAttribute(gnn_conv_kernel,
                         cudaFuncAttributeMaxDynamicSharedMemorySize, smem_bytes);
    gnn_conv_kernel<<<N, 256, smem_bytes>>>(x, Ww, Wb, Bw, Bb, out);
    gather_relu_kernel<<<N, 256>>>(out);
}

// round 17
// speedup vs baseline: 1.5265x; 1.1000x over previous
#include <cuda_runtime.h>

// ---------------------------------------------------------------------------
// SpatioTemporalGNNLayer via conv linearity:
//   U = conv(x, Ww) + Wb + Bb   (kernel 1 -> d_out)
//   V = conv(x, Bw)             (kernel 1 -> g_V)
//   out = relu(U[dst] + mean_{src} V[src])   (kernel 2, CSR gather)
//
// Conv kernel (R17): thread = 2cos x 2sets x 4px x 2rows, all 16 ci (no
// reduction). Weights stored SCALAR in smem (LDS.64/tap), duplicated into
// f32x2 pairs via register MOVs on the alu pipe; S-pairs packed from P regs
// (no S smem region). Conflict-free 96B rows. 256 thr x 2 CTA/SM.
// ---------------------------------------------------------------------------

#define NNODES 4096
#define NODE_ELEMS 4096          // 16*16*16
#define RS 24                    // row: [0, x0..x15, 0, pad..] = 96B
#define CHS (18*RS)              // 432 words per channel image
#define IMG_FLOATS (16*CHS)      // 6912
#define WT_FLOATS 4608           // 16ci*9tap*8cog*4 scalars
#define NMASK (NNODES-1)

typedef unsigned long long ull;

__device__ int g_deg[NNODES];
__device__ int g_cur[NNODES];
__device__ int g_off[NNODES + 1];
__device__ int g_srcs[16384 * 4];
__device__ int g_is64;
__device__ float g_V[(size_t)NNODES * NODE_ELEMS];   // 67MB scratch for V

// ---------------------------------------------------------------------------
__global__ void prep_kernel(const int* __restrict__ ei32, int E) {
    int i = blockIdx.x * blockDim.x + threadIdx.x;
    if (i < NNODES) { g_deg[i] = 0; g_cur[i] = 0; }
    if (blockIdx.x == 0 && threadIdx.x < 32) {
        int n = (E < 32) ? E : 32;
        int odd = (threadIdx.x < n) ? ei32[2 * threadIdx.x + 1] : 0;
        unsigned nz = __ballot_sync(0xffffffffu, odd != 0);
        if (threadIdx.x == 0) g_is64 = (nz == 0);
    }
}

__device__ __forceinline__ int load_idx(const int* ei32, int pos) {
    return g_is64 ? (ei32[2 * pos] & NMASK) : (ei32[pos] & NMASK);
}

__global__ void count_kernel(const int* __restrict__ ei32, int E) {
    int e = blockIdx.x * blockDim.x + threadIdx.x;
    if (e < E) atomicAdd(&g_deg[load_idx(ei32, E + e)], 1);
}

__global__ void scanfill_kernel(const int* __restrict__ ei32, int E) {
    __shared__ int wsum[32];
    int t = threadIdx.x;
    int lane = t & 31, wid = t >> 5;
    int4 v = ((const int4*)g_deg)[t];
    int sum = v.x + v.y + v.z + v.w;
    int s = sum;
#pragma unroll
    for (int d = 1; d < 32; d <<= 1) {
        int n = __shfl_up_sync(0xffffffffu, s, d);
        if (lane >= d) s += n;
    }
    if (lane == 31) wsum[wid] = s;
    __syncthreads();
    if (wid == 0) {
        int ws = wsum[lane];
#pragma unroll
        for (int d = 1; d < 32; d <<= 1) {
            int n = __shfl_up_sync(0xffffffffu, ws, d);
            if (lane >= d) ws += n;
        }
        wsum[lane] = ws;
    }
    __syncthreads();
    int excl = ((wid > 0) ? wsum[wid - 1] : 0) + s - sum;
    g_off[4 * t + 0] = excl;
    g_off[4 * t + 1] = excl + v.x;
    g_off[4 * t + 2] = excl + v.x + v.y;
    g_off[4 * t + 3] = excl + v.x + v.y + v.z;
    if (t == 1023) g_off[NNODES] = wsum[31];
    __syncthreads();
    for (int e = t; e < E; e += 1024) {
        int sc = load_idx(ei32, e);
        int d  = load_idx(ei32, E + e);
        int pos = g_off[d] + atomicAdd(&g_cur[d], 1);
        g_srcs[pos] = sc;
    }
}

// ---------------------------------------------------------------------------
__device__ __forceinline__ void ffma2u(ull& d, ull a, ull b) {
    asm("fma.rn.f32x2 %0, %1, %2, %0;" : "+l"(d) : "l"(a), "l"(b));
}
__device__ __forceinline__ float2 u2f(ull v) {
    float2 f;
    asm("mov.b64 {%0, %1}, %2;" : "=f"(f.x), "=f"(f.y) : "l"(v));
    return f;
}
__device__ __forceinline__ ull f2u(float lo, float hi) {
    ull v;
    asm("mov.b64 %0, {%1, %2};" : "=l"(v) : "f"(lo), "f"(hi));
    return v;
}

__global__ __launch_bounds__(256, 2) void gnn_conv_kernel(
    const float* __restrict__ x,
    const float* __restrict__ Ww, const float* __restrict__ Wbias,
    const float* __restrict__ Bw, const float* __restrict__ Bbias,
    float* __restrict__ outU) {
    extern __shared__ float sm[];
    float* sImg = sm;                 // 6912 floats (padded P-only rows)
    float* sWt  = sm + IMG_FLOATS;    // 4608 floats (scalar weights)

    int tid  = threadIdx.x;
    int node = blockIdx.x;

    // zero pads: rows 0 and 17 (words 0..17) of every channel
    for (int i = tid; i < 16 * 36; i += 256) {
        int ch = i / 36, k = i % 36;
        int rowb = (k < 18) ? 0 : 17 * RS;
        sImg[ch * CHS + rowb + (k % 18)] = 0.f;
    }
    // word 0 and 17 of rows 1..16 of every channel
    if (tid < 16 * 16) {
        int ch = tid >> 4, y = tid & 15;
        float* b = sImg + ch * CHS + (y + 1) * RS;
        b[0] = 0.f; b[17] = 0.f;
    }
    // stage scalar weights: sWt[((ci*9+tap)*8 + m)*4 + s]
    //   s=0: Ww[2m], s=1: Ww[2m+1], s=2: Bw[2m], s=3: Bw[2m+1], q9 = ci*9+tap
    for (int i = tid; i < WT_FLOATS; i += 256) {
        int s  = i & 3;
        int t4 = i >> 2;
        int m  = t4 & 7;
        int q9 = t4 >> 3;
        int co = 2 * m + (s & 1);
        sWt[i] = (s >= 2) ? Bw[co * 144 + q9] : Ww[co * 144 + q9];
    }

    // scatter x[node] into padded rows (4 float4 per thread)
    const float4* xp = (const float4*)(x + (size_t)node * NODE_ELEMS);
    __syncthreads();   // pads zeroed before data stores
#pragma unroll
    for (int k = 0; k < 4; k++) {
        int i4  = tid + 256 * k;
        int ci  = i4 >> 6;
        int rem = i4 & 63;
        int y   = rem >> 2;
        int m   = (rem & 3) * 4;
        float* b = sImg + ci * CHS + (y + 1) * RS + 1 + m;
        float4 xv = xp[i4];
        b[0] = xv.x; b[1] = xv.y; b[2] = xv.z; b[3] = xv.w;
    }
    __syncthreads();

    // thread map: tid = q(2b) | rg(3b) | cog(3b); lane = q + 4*rg
    int q   = tid & 3;           // pixel quarter: px 4q..4q+3 (pairs 2q,2q+1)
    int rg  = (tid >> 2) & 7;    // row pair: output rows 2rg, 2rg+1
    int cog = tid >> 5;          // co pair: cos {2cog, 2cog+1}, both sets
    int y0  = 2 * rg;

    // acc[c][row][j]: c = {0:(W,co0) 1:(W,co1) 2:(B,co0) 3:(B,co1)}
    ull acc[4][2][2];
#pragma unroll
    for (int c = 0; c < 4; c++)
#pragma unroll
        for (int rr = 0; rr < 2; rr++) { acc[c][rr][0] = 0ull; acc[c][rr][1] = 0ull; }

    const float* cb0 = sImg + y0 * RS + 4 * q;
    const ull*   wt0 = (const ull*)sWt + cog * 2;   // ull idx ((ci*9+tap)*8+cog)*2

#pragma unroll 2
    for (int ci = 0; ci < 16; ci++) {
        const float* cb = cb0 + ci * CHS;
        // load 4 buffer rows: P pairs (LDS.128 + LDS.64), build S by packing
        ull P[4][3], S[4][2];
#pragma unroll
        for (int rr = 0; rr < 4; rr++) {
            ulonglong2 pp = *(const ulonglong2*)(cb + rr * RS);
            ull p2 = *(const ull*)(cb + rr * RS + 4);
            P[rr][0] = pp.x; P[rr][1] = pp.y; P[rr][2] = p2;
            float2 fa = u2f(pp.x), fb = u2f(pp.y), fc = u2f(p2);
            S[rr][0] = f2u(fa.y, fb.x);
            S[rr][1] = f2u(fb.y, fc.x);
        }
        const ull* wci = wt0 + (ci * 9) * 16;   // tap stride = 8 cogs * 2 ull
#pragma unroll
        for (int r = 0; r < 3; r++) {
#pragma unroll
            for (int t = 0; t < 3; t++) {
                const ull* wp = wci + (r * 3 + t) * 16;
                float2 fw = u2f(wp[0]);          // (Ww co0, Ww co1)
                float2 fv = u2f(wp[1]);          // (Bw co0, Bw co1)
                ull w0 = f2u(fw.x, fw.x);
                ull w1 = f2u(fw.y, fw.y);
                ull b0 = f2u(fv.x, fv.x);
                ull b1 = f2u(fv.y, fv.y);
#pragma unroll
                for (int rr = 0; rr < 2; rr++) {
#pragma unroll
                    for (int j = 0; j < 2; j++) {
                        ull op = (t == 0) ? P[rr + r][j]
                               : (t == 1) ? S[rr + r][j]
                                          : P[rr + r][j + 1];
                        ffma2u(acc[0][rr][j], w0, op);
                        ffma2u(acc[1][rr][j], w1, op);
                        ffma2u(acc[2][rr][j], b0, op);
                        ffma2u(acc[3][rr][j], b1, op);
                    }
                }
            }
        }
    }

    // epilogue: store U (with biases) and V
    float* gV = g_V + (size_t)node * NODE_ELEMS;
#pragma unroll
    for (int c2 = 0; c2 < 2; c2++) {
        int co = 2 * cog + c2;
        float bz = __ldg(&Wbias[co]) + __ldg(&Bbias[co]);
#pragma unroll
        for (int rr = 0; rr < 2; rr++) {
            int off = co * 256 + (y0 + rr) * 16 + 4 * q;
            float2 u0 = u2f(acc[c2][rr][0]);
            float2 u1 = u2f(acc[c2][rr][1]);
            *(float4*)(outU + (size_t)node * NODE_ELEMS + off) =
                make_float4(u0.x + bz, u0.y + bz, u1.x + bz, u1.y + bz);
            float2 v0 = u2f(acc[2 + c2][rr][0]);
            float2 v1 = u2f(acc[2 + c2][rr][1]);
            *(float4*)(gV + off) = make_float4(v0.x, v0.y, v1.x, v1.y);
        }
    }
}

// ---------------------------------------------------------------------------
// kernel 2: out = relu(U[dst] + mean_src V[src]); in-place on d_out (U).
__global__ __launch_bounds__(256) void gather_relu_kernel(float* __restrict__ out) {
    int tid  = threadIdx.x;
    int node = blockIdx.x;
    float* op = out + (size_t)node * NODE_ELEMS;

    float4 vs[4];
#pragma unroll
    for (int k = 0; k < 4; k++) vs[k] = make_float4(0.f, 0.f, 0.f, 0.f);

    int beg = g_off[node], end = g_off[node + 1];
    for (int e = beg; e < end; e++) {
        int sc = g_srcs[e] & NMASK;
        const float4* vp = (const float4*)(g_V + (size_t)sc * NODE_ELEMS);
#pragma unroll
        for (int k = 0; k < 4; k++) {
            float4 v = __ldg(&vp[tid + 256 * k]);
            vs[k].x += v.x; vs[k].y += v.y; vs[k].z += v.z; vs[k].w += v.w;
        }
    }
    float inv = 1.0f / (float)max(end - beg, 1);
#pragma unroll
    for (int k = 0; k < 4; k++) {
        float4 u = ((const float4*)op)[tid + 256 * k];
        ((float4*)op)[tid + 256 * k] = make_float4(
            fmaxf(u.x + vs[k].x * inv, 0.f), fmaxf(u.y + vs[k].y * inv, 0.f),
            fmaxf(u.z + vs[k].z * inv, 0.f), fmaxf(u.w + vs[k].w * inv, 0.f));
    }
}

// ---------------------------------------------------------------------------
extern "C" void kernel_launch(void* const* d_in, const int* in_sizes, int n_in,
                              void* d_out, int out_size) {
    const float* x   = (const float*)d_in[0];
    const int*   ei  = (const int*)d_in[1];   // int32 view; prep detects dtype
    const float* Ww  = (const float*)d_in[2];
    const float* Wb  = (const float*)d_in[3];
    const float* Bw  = (const float*)d_in[4];
    const float* Bb  = (const float*)d_in[5];
    float*       out = (float*)d_out;

    int E = in_sizes[1] / 2;
    int N = in_sizes[0] / NODE_ELEMS;

    prep_kernel<<<(NNODES + 255) / 256, 256>>>(ei, E);
    count_kernel<<<(E + 255) / 256, 256>>>(ei, E);
    scanfill_kernel<<<1, 1024>>>(ei, E);

    int smem_bytes = (IMG_FLOATS + WT_FLOATS) * (int)sizeof(float);  // 46080
    cudaFuncSetAttribute(gnn_conv_kernel,
                         cudaFuncAttributeMaxDynamicSharedMemorySize, smem_bytes);
    gnn_conv_kernel<<<N, 256, smem_bytes>>>(x, Ww, Wb, Bw, Bb, out);
    gather_relu_kernel<<<N, 256>>>(out);
}